// round 5
// baseline (speedup 1.0000x reference)
#include <cuda_runtime.h>
#include <cuda_bf16.h>
#include <cstdint>

#define NN 100000
#define EE 3200000
#define HID 32
#define DIN 128

// ---------------- scratch (plain device globals, scalar access only) ----
__device__ float g_tmp[NN * HID];   // h @ W (gather source)
__device__ float g_acc[NN * HID];   // conv result
__device__ float g_h[NN * HID];     // post-BN activations
__device__ float g_deg[NN];         // weighted degree -> dinv
__device__ float g_selfnorm[NN];    // dinv[i]^2
__device__ int   g_cnt[NN];         // degree count, then CSR cursor
__device__ int   g_off[NN + 1];     // CSR offsets
__device__ int   g_srcrow[EE];      // CSR: source node of each incoming edge
__device__ float g_enorm[EE];       // CSR: dinv[src]*w*dinv[dst]
__device__ float g_stats[64];       // BN: per-col sum (0..31), sumsq (32..63)

// ---------------- prep: degree + histogram ----------------
__global__ void k_init(int n) {
    int i = blockIdx.x * blockDim.x + threadIdx.x;
    if (i < n) { g_deg[i] = 1.0f; g_cnt[i] = 0; }   // self-loop weight 1
}

__global__ void k_degree_hist(const int* __restrict__ ei,
                              const float* __restrict__ w, int e_cnt, int n) {
    int e = blockIdx.x * blockDim.x + threadIdx.x;
    if (e < e_cnt) {
        int c = ei[e_cnt + e];
        c = min(max(c, 0), n - 1);   // defensive clamp
        atomicAdd(&g_deg[c], w[e]);
        atomicAdd(&g_cnt[c], 1);
    }
}

__global__ void k_dinv(int n) {
    int i = blockIdx.x * blockDim.x + threadIdx.x;
    if (i < n) {
        float d = g_deg[i];
        float di = (d > 0.f) ? rsqrtf(d) : 0.f;
        g_deg[i] = di;
        g_selfnorm[i] = di * di;
    }
}

// single-block exclusive scan over g_cnt -> g_off; resets g_cnt to cursor.
__global__ void k_scan(int n, int e_cnt) {
    __shared__ int ssum[1024];
    int tid = threadIdx.x;
    int chunk = (n + 1023) >> 10;
    int beg = tid * chunk;
    int end = min(beg + chunk, n);
    int s = 0;
    for (int i = beg; i < end; i++) s += g_cnt[i];
    ssum[tid] = s;
    __syncthreads();
    for (int off = 1; off < 1024; off <<= 1) {
        int v = (tid >= off) ? ssum[tid - off] : 0;
        __syncthreads();
        ssum[tid] += v;
        __syncthreads();
    }
    int run = (tid == 0) ? 0 : ssum[tid - 1];
    for (int i = beg; i < end; i++) {
        int c = g_cnt[i];
        g_off[i] = run;
        g_cnt[i] = run;   // cursor for the scatter pass
        run += c;
    }
    if (tid == 0) g_off[n] = e_cnt;
}

__global__ void k_csr_scatter(const int* __restrict__ ei,
                              const float* __restrict__ w, int e_cnt, int n) {
    int e = blockIdx.x * blockDim.x + threadIdx.x;
    if (e < e_cnt) {
        int r = ei[e];
        int c = ei[e_cnt + e];
        r = min(max(r, 0), n - 1);   // defensive clamp
        c = min(max(c, 0), n - 1);
        int pos = atomicAdd(&g_cnt[c], 1);
        g_srcrow[pos] = r;
        g_enorm[pos]  = g_deg[r] * w[e] * g_deg[c];
    }
}

// ---------------- transforms (h @ W) ----------------
// layer 0: x [N,128] @ W0 [128,32]. 8 warps/block, 1 row/warp, scalar loads.
__global__ void k_gemm128(const float* __restrict__ x,
                          const float* __restrict__ W, int n) {
    __shared__ float Ws[DIN * HID];
    __shared__ float xs[8][DIN];
    int tid = threadIdx.x;
    for (int i = tid; i < DIN * HID; i += 256) Ws[i] = W[i];
    __syncthreads();
    int warp = tid >> 5, lane = tid & 31;
    int r = blockIdx.x * 8 + warp;
    if (r >= n) return;
#pragma unroll
    for (int j = 0; j < 4; j++)
        xs[warp][j * 32 + lane] = x[r * DIN + j * 32 + lane];  // coalesced
    __syncwarp();
    float sum = 0.f;
#pragma unroll
    for (int k = 0; k < DIN; k++) sum += xs[warp][k] * Ws[k * HID + lane];
    g_tmp[r * HID + lane] = sum;
}

// layers 1-3: g_h [N,32] @ W [32,32]
__global__ void k_gemm32(const float* __restrict__ W, int n) {
    __shared__ float Ws[HID * HID];
    int tid = threadIdx.x;
    for (int i = tid; i < HID * HID; i += 256) Ws[i] = W[i];
    __syncthreads();
    int warp = tid >> 5, lane = tid & 31;
    int r = blockIdx.x * 8 + warp;
    if (r >= n) return;
    float mine = g_h[r * HID + lane];
    float sum = 0.f;
#pragma unroll
    for (int k = 0; k < HID; k++) {
        float xv = __shfl_sync(0xffffffffu, mine, k);
        sum += xv * Ws[k * HID + lane];
    }
    g_tmp[r * HID + lane] = sum;
}

// ---------------- CSR gather-aggregate (atomic-free) ----------------
// one warp per node; lane = feature column. Edge metadata loads are
// warp-uniform (broadcast); feature-row loads are fully coalesced (128B).
__global__ void k_aggregate(const float* __restrict__ b, int n) {
    int gid = blockIdx.x * blockDim.x + threadIdx.x;
    int v = gid >> 5;           // node = warp
    if (v >= n) return;
    int lane = gid & 31;
    int beg = g_off[v];
    int end = g_off[v + 1];
    // self loop + bias
    float acc = b[lane] + g_selfnorm[v] * g_tmp[v * HID + lane];
    for (int i = beg; i < end; i++) {
        int   r  = g_srcrow[i];
        float nm = g_enorm[i];
        acc += nm * g_tmp[r * HID + lane];
    }
    g_acc[v * HID + lane] = acc;
}

// ---------------- batchnorm ----------------
__global__ void k_zero_stats() {
    if (threadIdx.x < 64) g_stats[threadIdx.x] = 0.f;
}

__global__ void k_bnstats(int n) {
    int c = threadIdx.x & 31;
    int warp = threadIdx.x >> 5;         // 8 warps
    float s = 0.f, s2 = 0.f;
    for (int r = blockIdx.x * 8 + warp; r < n; r += gridDim.x * 8) {
        float v = g_acc[r * HID + c];
        s += v; s2 += v * v;
    }
    __shared__ float sh[8][64];
    sh[warp][c] = s;
    sh[warp][32 + c] = s2;
    __syncthreads();
    if (threadIdx.x < 64) {
        float t = 0.f;
#pragma unroll
        for (int w = 0; w < 8; w++) t += sh[w][threadIdx.x];
        atomicAdd(&g_stats[threadIdx.x], t);
    }
}

__global__ void k_bnrelu(const float* __restrict__ g,
                         const float* __restrict__ be, int n, float invN) {
    int idx = blockIdx.x * blockDim.x + threadIdx.x;
    if (idx >= n * HID) return;
    int c = idx & 31;
    float mu  = g_stats[c] * invN;
    float var = g_stats[32 + c] * invN - mu * mu;
    float v = (g_acc[idx] - mu) * rsqrtf(var + 1e-5f) * g[c] + be[c];
    g_h[idx] = fmaxf(v, 0.f);
}

__global__ void k_relu_out(float* __restrict__ out, int n) {
    int idx = blockIdx.x * blockDim.x + threadIdx.x;
    if (idx < n * HID) out[idx] = fmaxf(g_acc[idx], 0.f);
}

// ---------------- launch ----------------
extern "C" void kernel_launch(void* const* d_in, const int* in_sizes, int n_in,
                              void* d_out, int out_size) {
    const float* x  = (const float*)d_in[0];
    const int*   ei = (const int*)d_in[1];     // int32! (harness downcasts int64)
    const float* w  = (const float*)d_in[2];
    const float* W0 = (const float*)d_in[3];
    const float* b0 = (const float*)d_in[4];
    const float* W1 = (const float*)d_in[5];
    const float* b1 = (const float*)d_in[6];
    const float* W2 = (const float*)d_in[7];
    const float* b2 = (const float*)d_in[8];
    const float* W3 = (const float*)d_in[9];
    const float* b3 = (const float*)d_in[10];
    const float* g0 = (const float*)d_in[11];
    const float* be0 = (const float*)d_in[12];
    const float* g1 = (const float*)d_in[13];
    const float* be1 = (const float*)d_in[14];
    const float* g2 = (const float*)d_in[15];
    const float* be2 = (const float*)d_in[16];
    float* out = (float*)d_out;

    const int n = in_sizes[0] / DIN;        // 100000
    const int e = in_sizes[2];              // 3200000 (edge_weight count)
    const float invN = 1.0f / (float)n;

    const int TB = 256;
    const int gN   = (n + TB - 1) / TB;
    const int gE   = (e + TB - 1) / TB;
    const int gNH  = (n * HID + TB - 1) / TB;
    const int gAgg = (n * 32 + TB - 1) / TB;   // one warp per node
    const int gRow = (n + 7) / 8;              // 8 rows/block

    // ---- CSR + normalization precompute (reused by all 4 layers) ----
    k_init<<<gN, TB>>>(n);
    k_degree_hist<<<gE, TB>>>(ei, w, e, n);
    k_dinv<<<gN, TB>>>(n);
    k_scan<<<1, 1024>>>(n, e);
    k_csr_scatter<<<gE, TB>>>(ei, w, e, n);

    const float* Ws[4]  = {W0, W1, W2, W3};
    const float* bs[4]  = {b0, b1, b2, b3};
    const float* gs[3]  = {g0, g1, g2};
    const float* bes[3] = {be0, be1, be2};

    for (int layer = 0; layer < 4; layer++) {
        if (layer == 0)
            k_gemm128<<<gRow, TB>>>(x, Ws[0], n);
        else
            k_gemm32<<<gRow, TB>>>(Ws[layer], n);

        k_aggregate<<<gAgg, TB>>>(bs[layer], n);

        if (layer < 3) {
            k_zero_stats<<<1, 64>>>();
            k_bnstats<<<512, TB>>>(n);
            k_bnrelu<<<gNH, TB>>>(gs[layer], bes[layer], n, invN);
        } else {
            k_relu_out<<<gNH, TB>>>(out, n);
        }
    }
}

// round 6
// speedup vs baseline: 1.2830x; 1.2830x over previous
#include <cuda_runtime.h>
#include <cuda_bf16.h>
#include <cstdint>

#define NN 100000
#define EE 3200000
#define HID 32
#define DIN 128
#define SCAN_B 256                       // elements per scan block

// ---------------- scratch ----------------
__device__ float g_tmp[NN * HID];   // h @ W (gather source)
__device__ float g_acc[NN * HID];   // conv result
__device__ float g_deg[NN];         // weighted degree -> dinv
__device__ float g_selfnorm[NN];    // dinv[i]^2
__device__ int   g_cnt[NN];         // degree count, then CSR cursor
__device__ int   g_off[NN + 1];     // CSR offsets
__device__ int2  g_edge[EE];        // CSR: {src, float-bits of norm}
__device__ int   g_bsum[512];       // scan: per-block sums
__device__ int   g_boff[512];       // scan: per-block offsets
__device__ float g_stats[64];       // BN: per-col sum (0..31), sumsq (32..63)

// ---------------- prep: degree + histogram ----------------
__global__ void k_init(int n) {
    int i = blockIdx.x * blockDim.x + threadIdx.x;
    if (i < n) { g_deg[i] = 1.0f; g_cnt[i] = 0; }   // self-loop weight 1
}

__global__ void k_degree_hist(const int* __restrict__ ei,
                              const float* __restrict__ w, int e_cnt, int n) {
    int e = blockIdx.x * blockDim.x + threadIdx.x;
    if (e < e_cnt) {
        int c = ei[e_cnt + e];
        c = min(max(c, 0), n - 1);
        atomicAdd(&g_deg[c], w[e]);
        atomicAdd(&g_cnt[c], 1);
    }
}

__global__ void k_dinv(int n) {
    int i = blockIdx.x * blockDim.x + threadIdx.x;
    if (i < n) {
        float d = g_deg[i];
        float di = (d > 0.f) ? rsqrtf(d) : 0.f;
        g_deg[i] = di;
        g_selfnorm[i] = di * di;
    }
}

// ---------------- decoupled 3-phase scan (replaces 144us serial scan) ----
__global__ void k_scan_a(int n) {          // per-block sums
    __shared__ int sh[SCAN_B];
    int i = blockIdx.x * SCAN_B + threadIdx.x;
    sh[threadIdx.x] = (i < n) ? g_cnt[i] : 0;
    __syncthreads();
    for (int off = SCAN_B / 2; off > 0; off >>= 1) {
        if (threadIdx.x < off) sh[threadIdx.x] += sh[threadIdx.x + off];
        __syncthreads();
    }
    if (threadIdx.x == 0) g_bsum[blockIdx.x] = sh[0];
}

__global__ void k_scan_b(int nb) {         // scan of block sums (1 block, 512 thr)
    __shared__ int sh[512];
    int tid = threadIdx.x;
    sh[tid] = (tid < nb) ? g_bsum[tid] : 0;
    __syncthreads();
    for (int off = 1; off < 512; off <<= 1) {
        int v = (tid >= off) ? sh[tid - off] : 0;
        __syncthreads();
        sh[tid] += v;
        __syncthreads();
    }
    if (tid < nb) g_boff[tid] = sh[tid] - g_bsum[tid];  // exclusive
}

__global__ void k_scan_c(int n, int e_cnt) {  // local scan + global offset
    __shared__ int sh[SCAN_B];
    int tid = threadIdx.x;
    int i = blockIdx.x * SCAN_B + tid;
    int c = (i < n) ? g_cnt[i] : 0;
    sh[tid] = c;
    __syncthreads();
    for (int off = 1; off < SCAN_B; off <<= 1) {
        int v = (tid >= off) ? sh[tid - off] : 0;
        __syncthreads();
        sh[tid] += v;
        __syncthreads();
    }
    if (i < n) {
        int off = g_boff[blockIdx.x] + sh[tid] - c;  // exclusive
        g_off[i] = off;
        g_cnt[i] = off;                              // cursor
    }
    if (blockIdx.x == 0 && tid == 0) g_off[n] = e_cnt;
}

__global__ void k_csr_scatter(const int* __restrict__ ei,
                              const float* __restrict__ w, int e_cnt, int n) {
    int e = blockIdx.x * blockDim.x + threadIdx.x;
    if (e < e_cnt) {
        int r = ei[e];
        int c = ei[e_cnt + e];
        r = min(max(r, 0), n - 1);
        c = min(max(c, 0), n - 1);
        int pos = atomicAdd(&g_cnt[c], 1);
        float nm = g_deg[r] * w[e] * g_deg[c];
        g_edge[pos] = make_int2(r, __float_as_int(nm));
    }
}

// ---------------- transforms (h @ W) ----------------
// layer 0: x [N,128] @ W0 [128,32]. 8 warps/block, 1 row/warp.
__global__ void k_gemm128(const float* __restrict__ x,
                          const float* __restrict__ W, int n) {
    __shared__ float Ws[DIN * HID];
    __shared__ float xs[8][DIN];
    int tid = threadIdx.x;
    for (int i = tid; i < DIN * HID; i += 256) Ws[i] = W[i];
    __syncthreads();
    int warp = tid >> 5, lane = tid & 31;
    int r = blockIdx.x * 8 + warp;
    if (r >= n) return;
#pragma unroll
    for (int j = 0; j < 4; j++)
        xs[warp][j * 32 + lane] = x[r * DIN + j * 32 + lane];
    __syncwarp();
    float sum = 0.f;
#pragma unroll
    for (int k = 0; k < DIN; k++) sum += xs[warp][k] * Ws[k * HID + lane];
    g_tmp[r * HID + lane] = sum;
}

// layers 1-3: BN(prev layer) + ReLU fused into the activation read,
// then [32x32] GEMM via warp shuffles.
__global__ void k_gemm32_bn(const float* __restrict__ W,
                            const float* __restrict__ g,
                            const float* __restrict__ be, int n, float invN) {
    __shared__ float Ws[HID * HID];
    __shared__ float bn_s[HID], bn_b[HID];
    int tid = threadIdx.x;
    for (int i = tid; i < HID * HID; i += 256) Ws[i] = W[i];
    if (tid < HID) {
        float mu  = g_stats[tid] * invN;
        float var = g_stats[32 + tid] * invN - mu * mu;
        float sc  = rsqrtf(var + 1e-5f) * g[tid];
        bn_s[tid] = sc;
        bn_b[tid] = be[tid] - mu * sc;
    }
    __syncthreads();
    int warp = tid >> 5, lane = tid & 31;
    int r = blockIdx.x * 8 + warp;
    if (r >= n) return;
    float mine = fmaxf(g_acc[r * HID + lane] * bn_s[lane] + bn_b[lane], 0.f);
    float sum = 0.f;
#pragma unroll
    for (int k = 0; k < HID; k++) {
        float xv = __shfl_sync(0xffffffffu, mine, k);
        sum += xv * Ws[k * HID + lane];
    }
    g_tmp[r * HID + lane] = sum;
}

// ---------------- CSR gather-aggregate + fused BN stats ----------------
// one warp per node; lane = feature column. 8 warps/block.
__global__ void k_aggregate(const float* __restrict__ b, int n, int do_stats) {
    int gid = blockIdx.x * blockDim.x + threadIdx.x;
    int v = gid >> 5;
    int lane = gid & 31;
    int warp = (threadIdx.x) >> 5;
    float acc = 0.f;
    if (v < n) {
        int beg = g_off[v];
        int end = g_off[v + 1];
        acc = b[lane] + g_selfnorm[v] * g_tmp[v * HID + lane];
        int i = beg;
        for (; i + 1 < end; i += 2) {
            int2 e0 = g_edge[i];
            int2 e1 = g_edge[i + 1];
            float f0 = g_tmp[e0.x * HID + lane];
            float f1 = g_tmp[e1.x * HID + lane];
            acc += __int_as_float(e0.y) * f0;
            acc += __int_as_float(e1.y) * f1;
        }
        if (i < end) {
            int2 e0 = g_edge[i];
            acc += __int_as_float(e0.y) * g_tmp[e0.x * HID + lane];
        }
        g_acc[v * HID + lane] = acc;
    }
    if (do_stats) {
        __shared__ float sh[8][64];
        float a = (v < n) ? acc : 0.f;
        sh[warp][lane]      = a;
        sh[warp][32 + lane] = a * a;
        __syncthreads();
        if (threadIdx.x < 64) {
            float t = 0.f;
#pragma unroll
            for (int w = 0; w < 8; w++) t += sh[w][threadIdx.x];
            atomicAdd(&g_stats[threadIdx.x], t);
        }
    }
}

__global__ void k_zero_stats() {
    if (threadIdx.x < 64) g_stats[threadIdx.x] = 0.f;
}

__global__ void k_relu_out(float* __restrict__ out, int n) {
    int idx = blockIdx.x * blockDim.x + threadIdx.x;
    if (idx < n * HID) out[idx] = fmaxf(g_acc[idx], 0.f);
}

// ---------------- launch ----------------
extern "C" void kernel_launch(void* const* d_in, const int* in_sizes, int n_in,
                              void* d_out, int out_size) {
    const float* x  = (const float*)d_in[0];
    const int*   ei = (const int*)d_in[1];     // int32 (harness dtype)
    const float* w  = (const float*)d_in[2];
    const float* W0 = (const float*)d_in[3];
    const float* b0 = (const float*)d_in[4];
    const float* W1 = (const float*)d_in[5];
    const float* b1 = (const float*)d_in[6];
    const float* W2 = (const float*)d_in[7];
    const float* b2 = (const float*)d_in[8];
    const float* W3 = (const float*)d_in[9];
    const float* b3 = (const float*)d_in[10];
    const float* g0 = (const float*)d_in[11];
    const float* be0 = (const float*)d_in[12];
    const float* g1 = (const float*)d_in[13];
    const float* be1 = (const float*)d_in[14];
    const float* g2 = (const float*)d_in[15];
    const float* be2 = (const float*)d_in[16];
    float* out = (float*)d_out;

    const int n = in_sizes[0] / DIN;        // 100000
    const int e = in_sizes[2];              // 3200000
    const float invN = 1.0f / (float)n;

    const int TB = 256;
    const int gN   = (n + TB - 1) / TB;
    const int gE   = (e + TB - 1) / TB;
    const int gNH  = (n * HID + TB - 1) / TB;
    const int gAgg = (n * 32 + TB - 1) / TB;   // one warp per node
    const int gRow = (n + 7) / 8;
    const int nb   = (n + SCAN_B - 1) / SCAN_B; // 391 scan blocks

    // ---- CSR + normalization precompute ----
    k_init<<<gN, TB>>>(n);
    k_degree_hist<<<gE, TB>>>(ei, w, e, n);
    k_dinv<<<gN, TB>>>(n);
    k_scan_a<<<nb, SCAN_B>>>(n);
    k_scan_b<<<1, 512>>>(nb);
    k_scan_c<<<nb, SCAN_B>>>(n, e);
    k_csr_scatter<<<gE, TB>>>(ei, w, e, n);

    const float* Ws[4]  = {W0, W1, W2, W3};
    const float* bs[4]  = {b0, b1, b2, b3};
    const float* gs[3]  = {g0, g1, g2};
    const float* bes[3] = {be0, be1, be2};

    for (int layer = 0; layer < 4; layer++) {
        if (layer == 0)
            k_gemm128<<<gRow, TB>>>(x, Ws[0], n);
        else
            k_gemm32_bn<<<gRow, TB>>>(Ws[layer], gs[layer - 1],
                                      bes[layer - 1], n, invN);
        if (layer < 3) {
            k_zero_stats<<<1, 64>>>();
            k_aggregate<<<gAgg, TB>>>(bs[layer], n, 1);
        } else {
            k_aggregate<<<gAgg, TB>>>(bs[layer], n, 0);
            k_relu_out<<<gNH, TB>>>(out, n);
        }
    }
}

// round 7
// speedup vs baseline: 1.3130x; 1.0234x over previous
#include <cuda_runtime.h>
#include <cuda_bf16.h>
#include <cstdint>

#define NN 100000
#define EE 3200000
#define HID 32
#define DIN 128
#define SCAN_B 256

// ---------------- scratch ----------------
__device__ float g_tmp[NN * HID];   // h @ W (gather source)
__device__ float g_acc[NN * HID];   // conv result
__device__ float g_deg[NN];         // weighted degree -> dinv
__device__ float g_selfnorm[NN];    // dinv[i]^2
__device__ int   g_cnt[NN];         // degree count, then CSR cursor
__device__ int   g_off[NN + 1];     // CSR offsets
__device__ int2  g_edge[EE];        // CSR: {src, float-bits of norm}
__device__ int   g_bsum[512];
__device__ int   g_boff[512];
__device__ float g_stats[64];       // BN: per-col sum (0..31), sumsq (32..63)

// ---------------- prep ----------------
__global__ void k_init(int n) {
    int i = blockIdx.x * blockDim.x + threadIdx.x;
    if (i < n) { g_deg[i] = 1.0f; g_cnt[i] = 0; }
}

__global__ void k_degree_hist(const int* __restrict__ ei,
                              const float* __restrict__ w, int e_cnt, int n) {
    int e = blockIdx.x * blockDim.x + threadIdx.x;
    if (e < e_cnt) {
        int c = ei[e_cnt + e];
        c = min(max(c, 0), n - 1);
        atomicAdd(&g_deg[c], w[e]);
        atomicAdd(&g_cnt[c], 1);
    }
}

__global__ void k_dinv(int n) {
    int i = blockIdx.x * blockDim.x + threadIdx.x;
    if (i < n) {
        float d = g_deg[i];
        float di = (d > 0.f) ? rsqrtf(d) : 0.f;
        g_deg[i] = di;
        g_selfnorm[i] = di * di;
    }
}

// ---------------- decoupled 3-phase scan ----------------
__global__ void k_scan_a(int n) {
    __shared__ int sh[SCAN_B];
    int i = blockIdx.x * SCAN_B + threadIdx.x;
    sh[threadIdx.x] = (i < n) ? g_cnt[i] : 0;
    __syncthreads();
    for (int off = SCAN_B / 2; off > 0; off >>= 1) {
        if (threadIdx.x < off) sh[threadIdx.x] += sh[threadIdx.x + off];
        __syncthreads();
    }
    if (threadIdx.x == 0) g_bsum[blockIdx.x] = sh[0];
}

__global__ void k_scan_b(int nb) {
    __shared__ int sh[512];
    int tid = threadIdx.x;
    sh[tid] = (tid < nb) ? g_bsum[tid] : 0;
    __syncthreads();
    for (int off = 1; off < 512; off <<= 1) {
        int v = (tid >= off) ? sh[tid - off] : 0;
        __syncthreads();
        sh[tid] += v;
        __syncthreads();
    }
    if (tid < nb) g_boff[tid] = sh[tid] - g_bsum[tid];
}

__global__ void k_scan_c(int n, int e_cnt) {
    __shared__ int sh[SCAN_B];
    int tid = threadIdx.x;
    int i = blockIdx.x * SCAN_B + tid;
    int c = (i < n) ? g_cnt[i] : 0;
    sh[tid] = c;
    __syncthreads();
    for (int off = 1; off < SCAN_B; off <<= 1) {
        int v = (tid >= off) ? sh[tid - off] : 0;
        __syncthreads();
        sh[tid] += v;
        __syncthreads();
    }
    if (i < n) {
        int off = g_boff[blockIdx.x] + sh[tid] - c;
        g_off[i] = off;
        g_cnt[i] = off;
    }
    if (blockIdx.x == 0 && tid == 0) g_off[n] = e_cnt;
}

__global__ void k_csr_scatter(const int* __restrict__ ei,
                              const float* __restrict__ w, int e_cnt, int n) {
    int e = blockIdx.x * blockDim.x + threadIdx.x;
    if (e < e_cnt) {
        int r = ei[e];
        int c = ei[e_cnt + e];
        r = min(max(r, 0), n - 1);
        c = min(max(c, 0), n - 1);
        int pos = atomicAdd(&g_cnt[c], 1);
        float nm = g_deg[r] * w[e] * g_deg[c];
        g_edge[pos] = make_int2(r, __float_as_int(nm));
    }
}

// ---------------- transforms ----------------
__global__ void k_gemm128(const float* __restrict__ x,
                          const float* __restrict__ W, int n) {
    __shared__ float Ws[DIN * HID];
    __shared__ float xs[8][DIN];
    int tid = threadIdx.x;
    for (int i = tid; i < DIN * HID; i += 256) Ws[i] = W[i];
    __syncthreads();
    int warp = tid >> 5, lane = tid & 31;
    int r = blockIdx.x * 8 + warp;
    if (r >= n) return;
#pragma unroll
    for (int j = 0; j < 4; j++)
        xs[warp][j * 32 + lane] = x[r * DIN + j * 32 + lane];
    __syncwarp();
    float sum = 0.f;
#pragma unroll
    for (int k = 0; k < DIN; k++) sum += xs[warp][k] * Ws[k * HID + lane];
    g_tmp[r * HID + lane] = sum;
}

__global__ void k_gemm32_bn(const float* __restrict__ W,
                            const float* __restrict__ g,
                            const float* __restrict__ be, int n, float invN) {
    __shared__ float Ws[HID * HID];
    __shared__ float bn_s[HID], bn_b[HID];
    int tid = threadIdx.x;
    for (int i = tid; i < HID * HID; i += 256) Ws[i] = W[i];
    if (tid < HID) {
        float mu  = g_stats[tid] * invN;
        float var = g_stats[32 + tid] * invN - mu * mu;
        float sc  = rsqrtf(var + 1e-5f) * g[tid];
        bn_s[tid] = sc;
        bn_b[tid] = be[tid] - mu * sc;
    }
    __syncthreads();
    int warp = tid >> 5, lane = tid & 31;
    int r = blockIdx.x * 8 + warp;
    if (r >= n) return;
    float mine = fmaxf(g_acc[r * HID + lane] * bn_s[lane] + bn_b[lane], 0.f);
    float sum = 0.f;
#pragma unroll
    for (int k = 0; k < HID; k++) {
        float xv = __shfl_sync(0xffffffffu, mine, k);
        sum += xv * Ws[k * HID + lane];
    }
    g_tmp[r * HID + lane] = sum;
}

// ---------------- CSR gather-aggregate, deep-unrolled for MLP ----------
// one warp per node; lane = feature column. 8 warps/block.
// out != nullptr => final layer: write relu(acc) to out, skip stats.
__global__ void k_aggregate(const float* __restrict__ b, int n, int do_stats,
                            float* __restrict__ out) {
    int gid = blockIdx.x * blockDim.x + threadIdx.x;
    int v = gid >> 5;
    int lane = gid & 31;
    int warp = threadIdx.x >> 5;
    float acc = 0.f;
    if (v < n) {
        int beg = g_off[v];
        int end = g_off[v + 1];
        acc = b[lane] + g_selfnorm[v] * g_tmp[v * HID + lane];
        int i = beg;
        // ---- unroll 8: batch metadata loads, then batch gathers ----
        for (; i + 8 <= end; i += 8) {
            int2 e0 = g_edge[i + 0];
            int2 e1 = g_edge[i + 1];
            int2 e2 = g_edge[i + 2];
            int2 e3 = g_edge[i + 3];
            int2 e4 = g_edge[i + 4];
            int2 e5 = g_edge[i + 5];
            int2 e6 = g_edge[i + 6];
            int2 e7 = g_edge[i + 7];
            float f0 = g_tmp[e0.x * HID + lane];
            float f1 = g_tmp[e1.x * HID + lane];
            float f2 = g_tmp[e2.x * HID + lane];
            float f3 = g_tmp[e3.x * HID + lane];
            float f4 = g_tmp[e4.x * HID + lane];
            float f5 = g_tmp[e5.x * HID + lane];
            float f6 = g_tmp[e6.x * HID + lane];
            float f7 = g_tmp[e7.x * HID + lane];
            acc += __int_as_float(e0.y) * f0;
            acc += __int_as_float(e1.y) * f1;
            acc += __int_as_float(e2.y) * f2;
            acc += __int_as_float(e3.y) * f3;
            acc += __int_as_float(e4.y) * f4;
            acc += __int_as_float(e5.y) * f5;
            acc += __int_as_float(e6.y) * f6;
            acc += __int_as_float(e7.y) * f7;
        }
        // ---- unroll 4 remainder ----
        if (i + 4 <= end) {
            int2 e0 = g_edge[i + 0];
            int2 e1 = g_edge[i + 1];
            int2 e2 = g_edge[i + 2];
            int2 e3 = g_edge[i + 3];
            float f0 = g_tmp[e0.x * HID + lane];
            float f1 = g_tmp[e1.x * HID + lane];
            float f2 = g_tmp[e2.x * HID + lane];
            float f3 = g_tmp[e3.x * HID + lane];
            acc += __int_as_float(e0.y) * f0;
            acc += __int_as_float(e1.y) * f1;
            acc += __int_as_float(e2.y) * f2;
            acc += __int_as_float(e3.y) * f3;
            i += 4;
        }
        // ---- scalar tail ----
        for (; i < end; i++) {
            int2 e0 = g_edge[i];
            acc += __int_as_float(e0.y) * g_tmp[e0.x * HID + lane];
        }
        if (out) out[v * HID + lane] = fmaxf(acc, 0.f);
        else     g_acc[v * HID + lane] = acc;
    }
    if (do_stats) {
        __shared__ float sh[8][64];
        float a = (v < n) ? acc : 0.f;
        sh[warp][lane]      = a;
        sh[warp][32 + lane] = a * a;
        __syncthreads();
        if (threadIdx.x < 64) {
            float t = 0.f;
#pragma unroll
            for (int w = 0; w < 8; w++) t += sh[w][threadIdx.x];
            atomicAdd(&g_stats[threadIdx.x], t);
        }
    }
}

__global__ void k_zero_stats() {
    if (threadIdx.x < 64) g_stats[threadIdx.x] = 0.f;
}

// ---------------- launch ----------------
extern "C" void kernel_launch(void* const* d_in, const int* in_sizes, int n_in,
                              void* d_out, int out_size) {
    const float* x  = (const float*)d_in[0];
    const int*   ei = (const int*)d_in[1];     // int32 (harness dtype)
    const float* w  = (const float*)d_in[2];
    const float* W0 = (const float*)d_in[3];
    const float* b0 = (const float*)d_in[4];
    const float* W1 = (const float*)d_in[5];
    const float* b1 = (const float*)d_in[6];
    const float* W2 = (const float*)d_in[7];
    const float* b2 = (const float*)d_in[8];
    const float* W3 = (const float*)d_in[9];
    const float* b3 = (const float*)d_in[10];
    const float* g0 = (const float*)d_in[11];
    const float* be0 = (const float*)d_in[12];
    const float* g1 = (const float*)d_in[13];
    const float* be1 = (const float*)d_in[14];
    const float* g2 = (const float*)d_in[15];
    const float* be2 = (const float*)d_in[16];
    float* out = (float*)d_out;

    const int n = in_sizes[0] / DIN;        // 100000
    const int e = in_sizes[2];              // 3200000
    const float invN = 1.0f / (float)n;

    const int TB = 256;
    const int gN   = (n + TB - 1) / TB;
    const int gE   = (e + TB - 1) / TB;
    const int gAgg = (n * 32 + TB - 1) / TB;
    const int gRow = (n + 7) / 8;
    const int nb   = (n + SCAN_B - 1) / SCAN_B;

    // ---- CSR + normalization precompute ----
    k_init<<<gN, TB>>>(n);
    k_degree_hist<<<gE, TB>>>(ei, w, e, n);
    k_dinv<<<gN, TB>>>(n);
    k_scan_a<<<nb, SCAN_B>>>(n);
    k_scan_b<<<1, 512>>>(nb);
    k_scan_c<<<nb, SCAN_B>>>(n, e);
    k_csr_scatter<<<gE, TB>>>(ei, w, e, n);

    const float* Ws[4]  = {W0, W1, W2, W3};
    const float* bs[4]  = {b0, b1, b2, b3};
    const float* gs[3]  = {g0, g1, g2};
    const float* bes[3] = {be0, be1, be2};

    for (int layer = 0; layer < 4; layer++) {
        if (layer == 0)
            k_gemm128<<<gRow, TB>>>(x, Ws[0], n);
        else
            k_gemm32_bn<<<gRow, TB>>>(Ws[layer], gs[layer - 1],
                                      bes[layer - 1], n, invN);
        if (layer < 3) {
            k_zero_stats<<<1, 64>>>();
            k_aggregate<<<gAgg, TB>>>(bs[layer], n, 1, nullptr);
        } else {
            k_aggregate<<<gAgg, TB>>>(bs[layer], n, 0, out);
        }
    }
}

// round 8
// speedup vs baseline: 1.3623x; 1.0376x over previous
#include <cuda_runtime.h>
#include <cuda_bf16.h>
#include <cstdint>

#define NN 100000
#define EE 3200000
#define HID 32
#define DIN 128
#define SCAN_B 256
#define AGG_T 512                         // threads per aggregate block
#define MAXB ((NN * 32 + AGG_T - 1) / AGG_T)   // 6250 aggregate blocks

// ---------------- scratch ----------------
__device__ float g_tmp[NN * HID];   // h @ W (gather source)
__device__ float g_acc[NN * HID];   // conv result
__device__ float g_deg[NN];         // weighted degree -> dinv
__device__ float g_selfnorm[NN];    // dinv[i]^2
__device__ int   g_cnt[NN];         // degree count, then CSR cursor
__device__ int   g_off[NN + 1];     // CSR offsets
__device__ int2  g_edge[EE];        // CSR: {src, float-bits of norm}
__device__ int   g_bsum[512];
__device__ int   g_boff[512];
__device__ float g_part[MAXB * 64]; // per-block partial BN stats
__device__ float g_stats[64];       // BN: per-col sum (0..31), sumsq (32..63)

// ---------------- prep ----------------
__global__ void k_init(int n) {
    int i = blockIdx.x * blockDim.x + threadIdx.x;
    if (i < n) { g_deg[i] = 1.0f; g_cnt[i] = 0; }
}

__global__ void k_degree_hist(const int* __restrict__ ei,
                              const float* __restrict__ w, int e_cnt, int n) {
    int e = blockIdx.x * blockDim.x + threadIdx.x;
    if (e < e_cnt) {
        int c = ei[e_cnt + e];
        c = min(max(c, 0), n - 1);
        atomicAdd(&g_deg[c], w[e]);
        atomicAdd(&g_cnt[c], 1);
    }
}

__global__ void k_dinv(int n) {
    int i = blockIdx.x * blockDim.x + threadIdx.x;
    if (i < n) {
        float d = g_deg[i];
        float di = (d > 0.f) ? rsqrtf(d) : 0.f;
        g_deg[i] = di;
        g_selfnorm[i] = di * di;
    }
}

// ---------------- decoupled 3-phase scan ----------------
__global__ void k_scan_a(int n) {
    __shared__ int sh[SCAN_B];
    int i = blockIdx.x * SCAN_B + threadIdx.x;
    sh[threadIdx.x] = (i < n) ? g_cnt[i] : 0;
    __syncthreads();
    for (int off = SCAN_B / 2; off > 0; off >>= 1) {
        if (threadIdx.x < off) sh[threadIdx.x] += sh[threadIdx.x + off];
        __syncthreads();
    }
    if (threadIdx.x == 0) g_bsum[blockIdx.x] = sh[0];
}

__global__ void k_scan_b(int nb) {
    __shared__ int sh[512];
    int tid = threadIdx.x;
    sh[tid] = (tid < nb) ? g_bsum[tid] : 0;
    __syncthreads();
    for (int off = 1; off < 512; off <<= 1) {
        int v = (tid >= off) ? sh[tid - off] : 0;
        __syncthreads();
        sh[tid] += v;
        __syncthreads();
    }
    if (tid < nb) g_boff[tid] = sh[tid] - g_bsum[tid];
}

__global__ void k_scan_c(int n, int e_cnt) {
    __shared__ int sh[SCAN_B];
    int tid = threadIdx.x;
    int i = blockIdx.x * SCAN_B + tid;
    int c = (i < n) ? g_cnt[i] : 0;
    sh[tid] = c;
    __syncthreads();
    for (int off = 1; off < SCAN_B; off <<= 1) {
        int v = (tid >= off) ? sh[tid - off] : 0;
        __syncthreads();
        sh[tid] += v;
        __syncthreads();
    }
    if (i < n) {
        int off = g_boff[blockIdx.x] + sh[tid] - c;
        g_off[i] = off;
        g_cnt[i] = off;
    }
    if (blockIdx.x == 0 && tid == 0) g_off[n] = e_cnt;
}

__global__ void k_csr_scatter(const int* __restrict__ ei,
                              const float* __restrict__ w, int e_cnt, int n) {
    int e = blockIdx.x * blockDim.x + threadIdx.x;
    if (e < e_cnt) {
        int r = ei[e];
        int c = ei[e_cnt + e];
        r = min(max(r, 0), n - 1);
        c = min(max(c, 0), n - 1);
        int pos = atomicAdd(&g_cnt[c], 1);
        float nm = g_deg[r] * w[e] * g_deg[c];
        g_edge[pos] = make_int2(r, __float_as_int(nm));
    }
}

// ---------------- transforms ----------------
__global__ void k_gemm128(const float* __restrict__ x,
                          const float* __restrict__ W, int n) {
    __shared__ float Ws[DIN * HID];
    __shared__ float xs[8][DIN];
    int tid = threadIdx.x;
    for (int i = tid; i < DIN * HID; i += 256) Ws[i] = W[i];
    __syncthreads();
    int warp = tid >> 5, lane = tid & 31;
    int r = blockIdx.x * 8 + warp;
    if (r >= n) return;
#pragma unroll
    for (int j = 0; j < 4; j++)
        xs[warp][j * 32 + lane] = x[r * DIN + j * 32 + lane];
    __syncwarp();
    float sum = 0.f;
#pragma unroll
    for (int k = 0; k < DIN; k++) sum += xs[warp][k] * Ws[k * HID + lane];
    g_tmp[r * HID + lane] = sum;
}

__global__ void k_gemm32_bn(const float* __restrict__ W,
                            const float* __restrict__ g,
                            const float* __restrict__ be, int n, float invN) {
    __shared__ float Ws[HID * HID];
    __shared__ float bn_s[HID], bn_b[HID];
    int tid = threadIdx.x;
    for (int i = tid; i < HID * HID; i += 256) Ws[i] = W[i];
    if (tid < HID) {
        float mu  = g_stats[tid] * invN;
        float var = g_stats[32 + tid] * invN - mu * mu;
        float sc  = rsqrtf(var + 1e-5f) * g[tid];
        bn_s[tid] = sc;
        bn_b[tid] = be[tid] - mu * sc;
    }
    __syncthreads();
    int warp = tid >> 5, lane = tid & 31;
    int r = blockIdx.x * 8 + warp;
    if (r >= n) return;
    float mine = fmaxf(g_acc[r * HID + lane] * bn_s[lane] + bn_b[lane], 0.f);
    float sum = 0.f;
#pragma unroll
    for (int k = 0; k < HID; k++) {
        float xv = __shfl_sync(0xffffffffu, mine, k);
        sum += xv * Ws[k * HID + lane];
    }
    g_tmp[r * HID + lane] = sum;
}

// ---------------- CSR gather-aggregate ----------------
// one warp per node; lane = feature column. 16 warps/block.
// BN stats written as per-block partials (NO contended atomics).
__global__ void __launch_bounds__(AGG_T)
k_aggregate(const float* __restrict__ b, int n, int do_stats,
            float* __restrict__ out) {
    int gid = blockIdx.x * AGG_T + threadIdx.x;
    int v = gid >> 5;
    int lane = gid & 31;
    int warp = threadIdx.x >> 5;
    float acc = 0.f;
    if (v < n) {
        int beg = g_off[v];
        int end = g_off[v + 1];
        acc = b[lane] + g_selfnorm[v] * g_tmp[v * HID + lane];
        int i = beg;
        for (; i + 8 <= end; i += 8) {
            int2 e0 = g_edge[i + 0];
            int2 e1 = g_edge[i + 1];
            int2 e2 = g_edge[i + 2];
            int2 e3 = g_edge[i + 3];
            int2 e4 = g_edge[i + 4];
            int2 e5 = g_edge[i + 5];
            int2 e6 = g_edge[i + 6];
            int2 e7 = g_edge[i + 7];
            float f0 = g_tmp[e0.x * HID + lane];
            float f1 = g_tmp[e1.x * HID + lane];
            float f2 = g_tmp[e2.x * HID + lane];
            float f3 = g_tmp[e3.x * HID + lane];
            float f4 = g_tmp[e4.x * HID + lane];
            float f5 = g_tmp[e5.x * HID + lane];
            float f6 = g_tmp[e6.x * HID + lane];
            float f7 = g_tmp[e7.x * HID + lane];
            acc += __int_as_float(e0.y) * f0;
            acc += __int_as_float(e1.y) * f1;
            acc += __int_as_float(e2.y) * f2;
            acc += __int_as_float(e3.y) * f3;
            acc += __int_as_float(e4.y) * f4;
            acc += __int_as_float(e5.y) * f5;
            acc += __int_as_float(e6.y) * f6;
            acc += __int_as_float(e7.y) * f7;
        }
        if (i + 4 <= end) {
            int2 e0 = g_edge[i + 0];
            int2 e1 = g_edge[i + 1];
            int2 e2 = g_edge[i + 2];
            int2 e3 = g_edge[i + 3];
            float f0 = g_tmp[e0.x * HID + lane];
            float f1 = g_tmp[e1.x * HID + lane];
            float f2 = g_tmp[e2.x * HID + lane];
            float f3 = g_tmp[e3.x * HID + lane];
            acc += __int_as_float(e0.y) * f0;
            acc += __int_as_float(e1.y) * f1;
            acc += __int_as_float(e2.y) * f2;
            acc += __int_as_float(e3.y) * f3;
            i += 4;
        }
        for (; i < end; i++) {
            int2 e0 = g_edge[i];
            acc += __int_as_float(e0.y) * g_tmp[e0.x * HID + lane];
        }
        if (out) out[v * HID + lane] = fmaxf(acc, 0.f);
        else     g_acc[v * HID + lane] = acc;
    }
    if (do_stats) {
        __shared__ float sh[16][64];
        float a = (v < n) ? acc : 0.f;
        sh[warp][lane]      = a;
        sh[warp][32 + lane] = a * a;
        __syncthreads();
        if (threadIdx.x < 64) {
            float t = 0.f;
#pragma unroll
            for (int w = 0; w < 16; w++) t += sh[w][threadIdx.x];
            g_part[blockIdx.x * 64 + threadIdx.x] = t;   // no atomics
        }
    }
}

// one block per stat entry (64 blocks); reduce g_part column j.
__global__ void k_redstats(int nb) {
    __shared__ float sh[256];
    int j = blockIdx.x;
    int tid = threadIdx.x;
    float s = 0.f;
    for (int b2 = tid; b2 < nb; b2 += 256) s += g_part[b2 * 64 + j];
    sh[tid] = s;
    __syncthreads();
    for (int off = 128; off > 0; off >>= 1) {
        if (tid < off) sh[tid] += sh[tid + off];
        __syncthreads();
    }
    if (tid == 0) g_stats[j] = sh[0];
}

// ---------------- launch ----------------
extern "C" void kernel_launch(void* const* d_in, const int* in_sizes, int n_in,
                              void* d_out, int out_size) {
    const float* x  = (const float*)d_in[0];
    const int*   ei = (const int*)d_in[1];     // int32 (harness dtype)
    const float* w  = (const float*)d_in[2];
    const float* W0 = (const float*)d_in[3];
    const float* b0 = (const float*)d_in[4];
    const float* W1 = (const float*)d_in[5];
    const float* b1 = (const float*)d_in[6];
    const float* W2 = (const float*)d_in[7];
    const float* b2 = (const float*)d_in[8];
    const float* W3 = (const float*)d_in[9];
    const float* b3 = (const float*)d_in[10];
    const float* g0 = (const float*)d_in[11];
    const float* be0 = (const float*)d_in[12];
    const float* g1 = (const float*)d_in[13];
    const float* be1 = (const float*)d_in[14];
    const float* g2 = (const float*)d_in[15];
    const float* be2 = (const float*)d_in[16];
    float* out = (float*)d_out;

    const int n = in_sizes[0] / DIN;        // 100000
    const int e = in_sizes[2];              // 3200000
    const float invN = 1.0f / (float)n;

    const int TB = 256;
    const int gN   = (n + TB - 1) / TB;
    const int gE   = (e + TB - 1) / TB;
    const int gAgg = (n * 32 + AGG_T - 1) / AGG_T;  // 6250
    const int gRow = (n + 7) / 8;
    const int nb   = (n + SCAN_B - 1) / SCAN_B;

    // ---- CSR + normalization precompute ----
    k_init<<<gN, TB>>>(n);
    k_degree_hist<<<gE, TB>>>(ei, w, e, n);
    k_dinv<<<gN, TB>>>(n);
    k_scan_a<<<nb, SCAN_B>>>(n);
    k_scan_b<<<1, 512>>>(nb);
    k_scan_c<<<nb, SCAN_B>>>(n, e);
    k_csr_scatter<<<gE, TB>>>(ei, w, e, n);

    const float* Ws[4]  = {W0, W1, W2, W3};
    const float* bs[4]  = {b0, b1, b2, b3};
    const float* gs[3]  = {g0, g1, g2};
    const float* bes[3] = {be0, be1, be2};

    for (int layer = 0; layer < 4; layer++) {
        if (layer == 0)
            k_gemm128<<<gRow, TB>>>(x, Ws[0], n);
        else
            k_gemm32_bn<<<gRow, TB>>>(Ws[layer], gs[layer - 1],
                                      bes[layer - 1], n, invN);
        if (layer < 3) {
            k_aggregate<<<gAgg, AGG_T>>>(bs[layer], n, 1, nullptr);
            k_redstats<<<64, 256>>>(gAgg);
        } else {
            k_aggregate<<<gAgg, AGG_T>>>(bs[layer], n, 0, out);
        }
    }
}